// round 1
// baseline (speedup 1.0000x reference)
#include <cuda_runtime.h>
#include <cuda_bf16.h>
#include <cstdint>

// Problem dims
#define M_DIM 8192     // B*S = 4*2048
#define N_DIM 4096     // D_OUT
#define K_DIM 4096     // D_IN
#define CAP_  1024

// GEMM tiling
#define BM 128
#define BN 128
#define BK 32
#define STAGES 3
#define PAD 40                  // smem row pitch (elements): 80B rows, conflict-free ldmatrix
#define KT (K_DIM / BK)
#define SMEM_BYTES (STAGES * 4 * BM * PAD * 2)   // 122880

// ---------------------------------------------------------------------------
// Scratch (static device memory — no runtime allocation)
// ---------------------------------------------------------------------------
__device__ __nv_bfloat16 g_Xh[(size_t)M_DIM * K_DIM];
__device__ __nv_bfloat16 g_Xl[(size_t)M_DIM * K_DIM];
__device__ __nv_bfloat16 g_Wh[(size_t)N_DIM * K_DIM];
__device__ __nv_bfloat16 g_Wl[(size_t)N_DIM * K_DIM];
__device__ float g_logits[CAP_];
__device__ float g_attn[CAP_];
__device__ float g_memout[N_DIM];

// ---------------------------------------------------------------------------
// Split fp32 -> bf16 hi + bf16 residual
// ---------------------------------------------------------------------------
__global__ void split_x_kernel(const float* __restrict__ x, int n2) {
    int i = blockIdx.x * blockDim.x + threadIdx.x;
    int stride = gridDim.x * blockDim.x;
    const float2* x2 = reinterpret_cast<const float2*>(x);
    __nv_bfloat162* hi2 = reinterpret_cast<__nv_bfloat162*>(g_Xh);
    __nv_bfloat162* lo2 = reinterpret_cast<__nv_bfloat162*>(g_Xl);
    for (; i < n2; i += stride) {
        float2 v = x2[i];
        __nv_bfloat16 h0 = __float2bfloat16(v.x);
        __nv_bfloat16 h1 = __float2bfloat16(v.y);
        hi2[i] = __halves2bfloat162(h0, h1);
        lo2[i] = __halves2bfloat162(__float2bfloat16(v.x - __bfloat162float(h0)),
                                    __float2bfloat16(v.y - __bfloat162float(h1)));
    }
}

__global__ void split_w_kernel(const float* __restrict__ w,
                               const float* __restrict__ scale, int n2) {
    int i = blockIdx.x * blockDim.x + threadIdx.x;
    int stride = gridDim.x * blockDim.x;
    const float2* w2 = reinterpret_cast<const float2*>(w);
    __nv_bfloat162* hi2 = reinterpret_cast<__nv_bfloat162*>(g_Wh);
    __nv_bfloat162* lo2 = reinterpret_cast<__nv_bfloat162*>(g_Wl);
    for (; i < n2; i += stride) {
        float2 v = w2[i];
        int row = i >> 11;               // (2*i) / 4096
        float s = scale[row];
        float a = v.x * s, b = v.y * s;
        __nv_bfloat16 h0 = __float2bfloat16(a);
        __nv_bfloat16 h1 = __float2bfloat16(b);
        hi2[i] = __halves2bfloat162(h0, h1);
        lo2[i] = __halves2bfloat162(__float2bfloat16(a - __bfloat162float(h0)),
                                    __float2bfloat16(b - __bfloat162float(h1)));
    }
}

// ---------------------------------------------------------------------------
// Associative memory: logits -> softmax -> weighted value sum
// ---------------------------------------------------------------------------
__global__ void logits_kernel(const float* __restrict__ keys,
                              const float* __restrict__ x /* q = x[0,0,:] */) {
    int c = blockIdx.x;
    const float* kr = keys + (size_t)c * K_DIM;
    float s = 0.f;
    for (int i = threadIdx.x; i < K_DIM; i += 128) s += kr[i] * x[i];
    for (int o = 16; o; o >>= 1) s += __shfl_xor_sync(0xffffffffu, s, o);
    __shared__ float red[4];
    if ((threadIdx.x & 31) == 0) red[threadIdx.x >> 5] = s;
    __syncthreads();
    if (threadIdx.x == 0) g_logits[c] = red[0] + red[1] + red[2] + red[3];
}

__global__ void softmax_kernel() {
    int t = threadIdx.x;   // CAP_ threads
    float v = g_logits[t];
    __shared__ float red[32];
    __shared__ float stat;
    float m = v;
    for (int o = 16; o; o >>= 1) m = fmaxf(m, __shfl_xor_sync(0xffffffffu, m, o));
    if ((t & 31) == 0) red[t >> 5] = m;
    __syncthreads();
    if (t < 32) {
        float mm = red[t];
        for (int o = 16; o; o >>= 1) mm = fmaxf(mm, __shfl_xor_sync(0xffffffffu, mm, o));
        if (t == 0) stat = mm;
    }
    __syncthreads();
    float e = __expf(v - stat);
    float s = e;
    for (int o = 16; o; o >>= 1) s += __shfl_xor_sync(0xffffffffu, s, o);
    __syncthreads();
    if ((t & 31) == 0) red[t >> 5] = s;
    __syncthreads();
    if (t < 32) {
        float ss = red[t];
        for (int o = 16; o; o >>= 1) ss += __shfl_xor_sync(0xffffffffu, ss, o);
        if (t == 0) stat = ss;
    }
    __syncthreads();
    g_attn[t] = e / stat;
}

__global__ void memout_kernel(const float* __restrict__ V) {
    __shared__ float sa[CAP_];
    for (int i = threadIdx.x; i < CAP_; i += blockDim.x) sa[i] = g_attn[i];
    __syncthreads();
    int o = blockIdx.x * blockDim.x + threadIdx.x;
    float s = 0.f;
    #pragma unroll 4
    for (int c = 0; c < CAP_; ++c) s += sa[c] * V[(size_t)c * N_DIM + o];
    g_memout[o] = s;
}

// ---------------------------------------------------------------------------
// Main GEMM: bf16 split-precision, cp.async 3-stage pipeline, mma.sync bf16
// out[m][n] = sum_k x[m][k]*w[n][k]  (~ xh*wh + xl*wh + xh*wl) + 0.01*memout[n]
// ---------------------------------------------------------------------------
__global__ __launch_bounds__(256, 1)
void gemm_kernel(float* __restrict__ out) {
    extern __shared__ char smem_raw[];
    __nv_bfloat16* smem = reinterpret_cast<__nv_bfloat16*>(smem_raw);

    const int tid = threadIdx.x;
    const int lane = tid & 31;
    const int warp = tid >> 5;
    const int wm = warp & 1;          // 2 warps along M  (64 rows each)
    const int wn = warp >> 1;         // 4 warps along N  (32 cols each)
    const int m0 = blockIdx.y * BM;
    const int n0 = blockIdx.x * BN;

    auto tile_base = [&](int s, int t) -> __nv_bfloat16* {
        return smem + ((size_t)s * 4 + t) * (BM * PAD);
    };

    const __nv_bfloat16* gbase[4] = {
        g_Xh + (size_t)m0 * K_DIM, g_Xl + (size_t)m0 * K_DIM,
        g_Wh + (size_t)n0 * K_DIM, g_Wl + (size_t)n0 * K_DIM };

    auto load_stage = [&](int kt, int s) {
        const int k0 = kt * BK;
        #pragma unroll
        for (int t = 0; t < 4; ++t) {
            __nv_bfloat16* smt = tile_base(s, t);
            #pragma unroll
            for (int i = 0; i < 2; ++i) {
                int c = tid + i * 256;       // 512 16B-chunks per tile
                int row = c >> 2, seg = c & 3;
                unsigned sa = (unsigned)__cvta_generic_to_shared(smt + row * PAD + seg * 8);
                const __nv_bfloat16* ga = gbase[t] + (size_t)row * K_DIM + k0 + seg * 8;
                asm volatile("cp.async.cg.shared.global [%0], [%1], 16;"
                             :: "r"(sa), "l"(ga));
            }
        }
    };

    float acc[4][4][4];
    #pragma unroll
    for (int mi = 0; mi < 4; ++mi)
        #pragma unroll
        for (int ni = 0; ni < 4; ++ni)
            #pragma unroll
            for (int r = 0; r < 4; ++r) acc[mi][ni][r] = 0.f;

    #pragma unroll
    for (int s = 0; s < STAGES - 1; ++s) {
        load_stage(s, s);
        asm volatile("cp.async.commit_group;");
    }

    for (int kt = 0; kt < KT; ++kt) {
        asm volatile("cp.async.wait_group %0;" :: "n"(STAGES - 2));
        __syncthreads();
        int nk = kt + STAGES - 1;
        if (nk < KT) load_stage(nk, nk % STAGES);
        asm volatile("cp.async.commit_group;");   // empty group near tail keeps wait semantics

        int cur = kt % STAGES;
        const __nv_bfloat16* sAh = tile_base(cur, 0);
        const __nv_bfloat16* sAl = tile_base(cur, 1);
        const __nv_bfloat16* sBh = tile_base(cur, 2);
        const __nv_bfloat16* sBl = tile_base(cur, 3);

        #pragma unroll
        for (int split = 0; split < 3; ++split) {
            const __nv_bfloat16* sA = (split == 1) ? sAl : sAh;
            const __nv_bfloat16* sB = (split == 2) ? sBl : sBh;
            #pragma unroll
            for (int ks = 0; ks < 2; ++ks) {
                unsigned af[4][4];
                #pragma unroll
                for (int mi = 0; mi < 4; ++mi) {
                    int r = wm * 64 + mi * 16 + (lane & 15);
                    int cc = ks * 16 + (lane >> 4) * 8;
                    unsigned ad = (unsigned)__cvta_generic_to_shared(sA + r * PAD + cc);
                    asm volatile("ldmatrix.sync.aligned.m8n8.x4.shared.b16 {%0,%1,%2,%3}, [%4];"
                                 : "=r"(af[mi][0]), "=r"(af[mi][1]),
                                   "=r"(af[mi][2]), "=r"(af[mi][3]) : "r"(ad));
                }
                unsigned bfr[4][2];
                #pragma unroll
                for (int ni = 0; ni < 4; ++ni) {
                    int r = wn * 32 + ni * 8 + (lane & 7);
                    int cc = ks * 16 + ((lane >> 3) & 1) * 8;
                    unsigned bd = (unsigned)__cvta_generic_to_shared(sB + r * PAD + cc);
                    asm volatile("ldmatrix.sync.aligned.m8n8.x2.shared.b16 {%0,%1}, [%2];"
                                 : "=r"(bfr[ni][0]), "=r"(bfr[ni][1]) : "r"(bd));
                }
                #pragma unroll
                for (int mi = 0; mi < 4; ++mi)
                    #pragma unroll
                    for (int ni = 0; ni < 4; ++ni)
                        asm volatile(
                            "mma.sync.aligned.m16n8k16.row.col.f32.bf16.bf16.f32 "
                            "{%0,%1,%2,%3}, {%4,%5,%6,%7}, {%8,%9}, {%0,%1,%2,%3};"
                            : "+f"(acc[mi][ni][0]), "+f"(acc[mi][ni][1]),
                              "+f"(acc[mi][ni][2]), "+f"(acc[mi][ni][3])
                            : "r"(af[mi][0]), "r"(af[mi][1]),
                              "r"(af[mi][2]), "r"(af[mi][3]),
                              "r"(bfr[ni][0]), "r"(bfr[ni][1]));
            }
        }
    }

    // Epilogue: add 0.01 * memory_out[n]
    const int g = lane >> 2, tg = lane & 3;
    #pragma unroll
    for (int ni = 0; ni < 4; ++ni) {
        int col = n0 + wn * 32 + ni * 8 + tg * 2;
        float b0 = 0.01f * g_memout[col];
        float b1 = 0.01f * g_memout[col + 1];
        #pragma unroll
        for (int mi = 0; mi < 4; ++mi) {
            int row = m0 + wm * 64 + mi * 16 + g;
            float2 v0 = make_float2(acc[mi][ni][0] + b0, acc[mi][ni][1] + b1);
            float2 v1 = make_float2(acc[mi][ni][2] + b0, acc[mi][ni][3] + b1);
            *reinterpret_cast<float2*>(out + (size_t)row * N_DIM + col) = v0;
            *reinterpret_cast<float2*>(out + (size_t)(row + 8) * N_DIM + col) = v1;
        }
    }
}

// ---------------------------------------------------------------------------
extern "C" void kernel_launch(void* const* d_in, const int* in_sizes, int n_in,
                              void* d_out, int out_size) {
    (void)in_sizes; (void)n_in; (void)out_size;
    const float* x  = (const float*)d_in[0];   // [4,2048,4096]
    const float* w  = (const float*)d_in[1];   // [4096,4096]
    const float* ws = (const float*)d_in[2];   // [4096,1]
    const float* mk = (const float*)d_in[3];   // [1024,4096]
    const float* mv = (const float*)d_in[4];   // [1024,4096]
    float* out = (float*)d_out;                // [4,2048,4096]

    split_x_kernel<<<2048, 256>>>(x, (M_DIM * K_DIM) / 2);
    split_w_kernel<<<2048, 256>>>(w, ws, (N_DIM * K_DIM) / 2);

    logits_kernel<<<CAP_, 128>>>(mk, x);
    softmax_kernel<<<1, CAP_>>>();
    memout_kernel<<<N_DIM / 256, 256>>>(mv);

    cudaFuncSetAttribute(gemm_kernel, cudaFuncAttributeMaxDynamicSharedMemorySize,
                         SMEM_BYTES);
    dim3 grid(N_DIM / BN, M_DIM / BM);   // 32 x 64 = 2048 CTAs
    gemm_kernel<<<grid, 256, SMEM_BYTES>>>(out);
}

// round 4
// speedup vs baseline: 1.6984x; 1.6984x over previous
#include <cuda_runtime.h>
#include <cuda_fp16.h>
#include <cstdint>

// Problem dims
#define M_DIM 8192
#define N_DIM 4096
#define K_DIM 4096
#define CAP_  1024

// GEMM tiling
#define BM 128
#define BN 128
#define BK 64
#define KT (K_DIM / BK)            // 64
#define STAGES 3
#define PAD 72                     // smem row pitch in elements (144B rows)
#define TILE_BYTES (128 * PAD * 2) // 18432
#define STAGE_BYTES (3 * TILE_BYTES)
#define SMEM_TOTAL (STAGES * STAGE_BYTES)   // 165888

#define OFF_A  0
#define OFF_BH TILE_BYTES
#define OFF_BL (2 * TILE_BYTES)

// ---------------------------------------------------------------------------
// Scratch (static device memory)
// ---------------------------------------------------------------------------
__device__ __half g_Xh[(size_t)M_DIM * K_DIM];   // x rounded to fp16
__device__ __half g_Wh[(size_t)N_DIM * K_DIM];   // scaled w, fp16 hi
__device__ __half g_Wl[(size_t)N_DIM * K_DIM];   // scaled w, fp16 residual
__device__ float g_logits[CAP_];
__device__ float g_attn[CAP_];
__device__ float g_memout[N_DIM];

// ---------------------------------------------------------------------------
__device__ __forceinline__ unsigned smem_u32(const void* p) {
    return (unsigned)__cvta_generic_to_shared(p);
}
__device__ __forceinline__ void cp16(unsigned sa, const void* ga) {
    asm volatile("cp.async.cg.shared.global [%0], [%1], 16;" :: "r"(sa), "l"(ga));
}

// ---------------------------------------------------------------------------
// Prep: x -> fp16; w*scale -> fp16 hi + fp16 residual
// ---------------------------------------------------------------------------
__global__ void split_x_kernel(const float* __restrict__ x, int n2) {
    int i = blockIdx.x * blockDim.x + threadIdx.x;
    int stride = gridDim.x * blockDim.x;
    const float2* x2 = reinterpret_cast<const float2*>(x);
    __half2* h2 = reinterpret_cast<__half2*>(g_Xh);
    for (; i < n2; i += stride) {
        float2 v = x2[i];
        h2[i] = __floats2half2_rn(v.x, v.y);
    }
}

__global__ void split_w_kernel(const float* __restrict__ w,
                               const float* __restrict__ scale, int n2) {
    int i = blockIdx.x * blockDim.x + threadIdx.x;
    int stride = gridDim.x * blockDim.x;
    const float2* w2 = reinterpret_cast<const float2*>(w);
    __half2* hi2 = reinterpret_cast<__half2*>(g_Wh);
    __half2* lo2 = reinterpret_cast<__half2*>(g_Wl);
    for (; i < n2; i += stride) {
        float2 v = w2[i];
        int row = i >> 11;             // (2*i)/4096
        float s = scale[row];
        float a = v.x * s, b = v.y * s;
        __half h0 = __float2half_rn(a);
        __half h1 = __float2half_rn(b);
        hi2[i] = __halves2half2(h0, h1);
        lo2[i] = __halves2half2(__float2half_rn(a - __half2float(h0)),
                                __float2half_rn(b - __half2float(h1)));
    }
}

// ---------------------------------------------------------------------------
// Associative memory: logits -> softmax -> weighted value sum
// ---------------------------------------------------------------------------
__global__ void logits_kernel(const float* __restrict__ keys,
                              const float* __restrict__ x) {
    int c = blockIdx.x;
    const float* kr = keys + (size_t)c * K_DIM;
    float s = 0.f;
    for (int i = threadIdx.x; i < K_DIM; i += 128) s += kr[i] * x[i];
    for (int o = 16; o; o >>= 1) s += __shfl_xor_sync(0xffffffffu, s, o);
    __shared__ float red[4];
    if ((threadIdx.x & 31) == 0) red[threadIdx.x >> 5] = s;
    __syncthreads();
    if (threadIdx.x == 0) g_logits[c] = red[0] + red[1] + red[2] + red[3];
}

__global__ void softmax_kernel() {
    int t = threadIdx.x;
    float v = g_logits[t];
    __shared__ float red[32];
    __shared__ float stat;
    float m = v;
    for (int o = 16; o; o >>= 1) m = fmaxf(m, __shfl_xor_sync(0xffffffffu, m, o));
    if ((t & 31) == 0) red[t >> 5] = m;
    __syncthreads();
    if (t < 32) {
        float mm = red[t];
        for (int o = 16; o; o >>= 1) mm = fmaxf(mm, __shfl_xor_sync(0xffffffffu, mm, o));
        if (t == 0) stat = mm;
    }
    __syncthreads();
    float e = __expf(v - stat);
    float s = e;
    for (int o = 16; o; o >>= 1) s += __shfl_xor_sync(0xffffffffu, s, o);
    __syncthreads();
    if ((t & 31) == 0) red[t >> 5] = s;
    __syncthreads();
    if (t < 32) {
        float ss = red[t];
        for (int o = 16; o; o >>= 1) ss += __shfl_xor_sync(0xffffffffu, ss, o);
        if (t == 0) stat = ss;
    }
    __syncthreads();
    g_attn[t] = e / stat;
}

__global__ void memout_kernel(const float* __restrict__ V) {
    __shared__ float sa[CAP_];
    for (int i = threadIdx.x; i < CAP_; i += blockDim.x) sa[i] = g_attn[i];
    __syncthreads();
    int o = blockIdx.x * blockDim.x + threadIdx.x;
    float s = 0.f;
    #pragma unroll 8
    for (int c = 0; c < CAP_; ++c) s += sa[c] * V[(size_t)c * N_DIM + o];
    g_memout[o] = s;
}

// ---------------------------------------------------------------------------
// GEMM: out[m][n] = xh[m]·(Wh[n] + Wl[n]) + 0.01*memout[n]
// fp16 inputs, fp32 accumulate, mma.sync m16n8k16
// ---------------------------------------------------------------------------
__device__ __forceinline__ void load_stage(char* smem, int s, int kt,
                                           int tid, int m0, int n0) {
    const int k0 = kt * BK;
    char* st = smem + s * STAGE_BYTES;
    const __half* gA  = g_Xh + (size_t)m0 * K_DIM + k0;
    const __half* gBh = g_Wh + (size_t)n0 * K_DIM + k0;
    const __half* gBl = g_Wl + (size_t)n0 * K_DIM + k0;
    // each tile = 128 rows x 8 chunks(16B) = 1024 chunks; 3 tiles = 3072 = 256*12
    #pragma unroll
    for (int i = 0; i < 4; ++i) {
        int idx = tid + i * 256;
        int row = idx >> 3, c = idx & 7;
        unsigned off = row * (PAD * 2) + c * 16;
        cp16(smem_u32(st + OFF_A  + off), gA  + (size_t)row * K_DIM + c * 8);
        cp16(smem_u32(st + OFF_BH + off), gBh + (size_t)row * K_DIM + c * 8);
        cp16(smem_u32(st + OFF_BL + off), gBl + (size_t)row * K_DIM + c * 8);
    }
}

__global__ __launch_bounds__(256, 1)
void gemm_kernel(float* __restrict__ out) {
    extern __shared__ char smem[];
    const int tid  = threadIdx.x;
    const int lane = tid & 31;
    const int warp = tid >> 5;
    const int wm = warp & 1;          // 2 warps along M (64 rows each)
    const int wn = warp >> 1;         // 4 warps along N (32 cols each)
    const int m0 = blockIdx.y * BM;
    const int n0 = blockIdx.x * BN;

    float acc[4][4][4];
    #pragma unroll
    for (int mi = 0; mi < 4; ++mi)
        #pragma unroll
        for (int ni = 0; ni < 4; ++ni)
            #pragma unroll
            for (int r = 0; r < 4; ++r) acc[mi][ni][r] = 0.f;

    load_stage(smem, 0, 0, tid, m0, n0);
    asm volatile("cp.async.commit_group;");
    load_stage(smem, 1, 1, tid, m0, n0);
    asm volatile("cp.async.commit_group;");

    // precomputed per-thread ldmatrix base offsets (element units)
    const int a_row = wm * 64 + (lane & 15);
    const int a_col = (lane >> 4) * 8;
    const int b_row = wn * 32 + (lane & 7);
    const int b_col = ((lane >> 3) & 1) * 8;

    for (int kt = 0; kt < KT; ++kt) {
        asm volatile("cp.async.wait_group %0;" :: "n"(STAGES - 2));
        __syncthreads();
        if (kt + 2 < KT) load_stage(smem, (kt + 2) % STAGES, kt + 2, tid, m0, n0);
        asm volatile("cp.async.commit_group;");

        char* st = smem + (kt % STAGES) * STAGE_BYTES;
        const __half* sA  = reinterpret_cast<const __half*>(st + OFF_A);
        const __half* sBh = reinterpret_cast<const __half*>(st + OFF_BH);
        const __half* sBl = reinterpret_cast<const __half*>(st + OFF_BL);

        unsigned af[2][4][4], bh[2][4][2], bl[2][4][2];

        auto load_frags = [&](int ks, int buf) {
            #pragma unroll
            for (int mi = 0; mi < 4; ++mi) {
                unsigned ad = smem_u32(sA + (a_row + mi * 16) * PAD + ks * 16 + a_col);
                asm volatile("ldmatrix.sync.aligned.m8n8.x4.shared.b16 {%0,%1,%2,%3}, [%4];"
                             : "=r"(af[buf][mi][0]), "=r"(af[buf][mi][1]),
                               "=r"(af[buf][mi][2]), "=r"(af[buf][mi][3]) : "r"(ad));
            }
            #pragma unroll
            for (int ni = 0; ni < 4; ++ni) {
                unsigned bd = smem_u32(sBh + (b_row + ni * 8) * PAD + ks * 16 + b_col);
                asm volatile("ldmatrix.sync.aligned.m8n8.x2.shared.b16 {%0,%1}, [%2];"
                             : "=r"(bh[buf][ni][0]), "=r"(bh[buf][ni][1]) : "r"(bd));
                unsigned cd = smem_u32(sBl + (b_row + ni * 8) * PAD + ks * 16 + b_col);
                asm volatile("ldmatrix.sync.aligned.m8n8.x2.shared.b16 {%0,%1}, [%2];"
                             : "=r"(bl[buf][ni][0]), "=r"(bl[buf][ni][1]) : "r"(cd));
            }
        };

        load_frags(0, 0);
        #pragma unroll
        for (int ks = 0; ks < 4; ++ks) {
            int cur = ks & 1;
            if (ks < 3) load_frags(ks + 1, cur ^ 1);
            #pragma unroll
            for (int mi = 0; mi < 4; ++mi)
                #pragma unroll
                for (int ni = 0; ni < 4; ++ni) {
                    asm volatile(
                        "mma.sync.aligned.m16n8k16.row.col.f32.f16.f16.f32 "
                        "{%0,%1,%2,%3}, {%4,%5,%6,%7}, {%8,%9}, {%0,%1,%2,%3};"
                        : "+f"(acc[mi][ni][0]), "+f"(acc[mi][ni][1]),
                          "+f"(acc[mi][ni][2]), "+f"(acc[mi][ni][3])
                        : "r"(af[cur][mi][0]), "r"(af[cur][mi][1]),
                          "r"(af[cur][mi][2]), "r"(af[cur][mi][3]),
                          "r"(bh[cur][ni][0]), "r"(bh[cur][ni][1]));
                    asm volatile(
                        "mma.sync.aligned.m16n8k16.row.col.f32.f16.f16.f32 "
                        "{%0,%1,%2,%3}, {%4,%5,%6,%7}, {%8,%9}, {%0,%1,%2,%3};"
                        : "+f"(acc[mi][ni][0]), "+f"(acc[mi][ni][1]),
                          "+f"(acc[mi][ni][2]), "+f"(acc[mi][ni][3])
                        : "r"(af[cur][mi][0]), "r"(af[cur][mi][1]),
                          "r"(af[cur][mi][2]), "r"(af[cur][mi][3]),
                          "r"(bl[cur][ni][0]), "r"(bl[cur][ni][1]));
                }
        }
    }

    // Epilogue: add 0.01 * memory_out[n]
    const int g = lane >> 2, tg = lane & 3;
    #pragma unroll
    for (int ni = 0; ni < 4; ++ni) {
        int col = n0 + wn * 32 + ni * 8 + tg * 2;
        float b0 = 0.01f * g_memout[col];
        float b1 = 0.01f * g_memout[col + 1];
        #pragma unroll
        for (int mi = 0; mi < 4; ++mi) {
            int row = m0 + wm * 64 + mi * 16 + g;
            float2 v0 = make_float2(acc[mi][ni][0] + b0, acc[mi][ni][1] + b1);
            float2 v1 = make_float2(acc[mi][ni][2] + b0, acc[mi][ni][3] + b1);
            *reinterpret_cast<float2*>(out + (size_t)row * N_DIM + col) = v0;
            *reinterpret_cast<float2*>(out + (size_t)(row + 8) * N_DIM + col) = v1;
        }
    }
}

// ---------------------------------------------------------------------------
extern "C" void kernel_launch(void* const* d_in, const int* in_sizes, int n_in,
                              void* d_out, int out_size) {
    (void)in_sizes; (void)n_in; (void)out_size;
    const float* x  = (const float*)d_in[0];
    const float* w  = (const float*)d_in[1];
    const float* ws = (const float*)d_in[2];
    const float* mk = (const float*)d_in[3];
    const float* mv = (const float*)d_in[4];
    float* out = (float*)d_out;

    split_x_kernel<<<2048, 256>>>(x, (M_DIM * K_DIM) / 2);
    split_w_kernel<<<2048, 256>>>(w, ws, (N_DIM * K_DIM) / 2);

    logits_kernel<<<CAP_, 128>>>(mk, x);
    softmax_kernel<<<1, CAP_>>>();
    memout_kernel<<<N_DIM / 256, 256>>>(mv);

    cudaFuncSetAttribute(gemm_kernel, cudaFuncAttributeMaxDynamicSharedMemorySize,
                         SMEM_TOTAL);
    dim3 grid(N_DIM / BN, M_DIM / BM);   // 32 x 64 = 2048 CTAs
    gemm_kernel<<<grid, 256, SMEM_TOTAL>>>(out);
}

// round 5
// speedup vs baseline: 3.2292x; 1.9013x over previous
#include <cuda_runtime.h>
#include <cuda_fp16.h>
#include <cstdint>

// Problem dims
#define M_DIM 8192
#define N_DIM 4096
#define K_DIM 4096
#define CAP_  1024

// GEMM tiling
#define BM 128
#define BN 128
#define BK 64
#define KT (K_DIM / BK)            // 64
#define STAGES 3
#define PAD 72                     // smem row pitch in elements (144B rows)
#define TILE_BYTES (128 * PAD * 2) // 18432
#define STAGE_BYTES (2 * TILE_BYTES)          // A + B = 36864
#define SMEM_TOTAL (STAGES * STAGE_BYTES)     // 110592 -> 2 CTAs/SM

#define OFF_A 0
#define OFF_B TILE_BYTES

// ---------------------------------------------------------------------------
// Scratch (static device memory)
// ---------------------------------------------------------------------------
__device__ __half g_Xh[(size_t)M_DIM * K_DIM];   // x rounded to fp16
__device__ __half g_Wh[(size_t)N_DIM * K_DIM];   // w*scale rounded to fp16
__device__ float g_logits[CAP_];
__device__ float g_attn[CAP_];
__device__ float g_memout[N_DIM];

// ---------------------------------------------------------------------------
__device__ __forceinline__ unsigned smem_u32(const void* p) {
    return (unsigned)__cvta_generic_to_shared(p);
}
__device__ __forceinline__ void cp16(unsigned sa, const void* ga) {
    asm volatile("cp.async.cg.shared.global [%0], [%1], 16;" :: "r"(sa), "l"(ga));
}

// ---------------------------------------------------------------------------
// Prep: x -> fp16; w*scale -> fp16
// ---------------------------------------------------------------------------
__global__ void split_x_kernel(const float* __restrict__ x, int n2) {
    int i = blockIdx.x * blockDim.x + threadIdx.x;
    int stride = gridDim.x * blockDim.x;
    const float2* x2 = reinterpret_cast<const float2*>(x);
    __half2* h2 = reinterpret_cast<__half2*>(g_Xh);
    for (; i < n2; i += stride) {
        float2 v = x2[i];
        h2[i] = __floats2half2_rn(v.x, v.y);
    }
}

__global__ void split_w_kernel(const float* __restrict__ w,
                               const float* __restrict__ scale, int n2) {
    int i = blockIdx.x * blockDim.x + threadIdx.x;
    int stride = gridDim.x * blockDim.x;
    const float2* w2 = reinterpret_cast<const float2*>(w);
    __half2* hi2 = reinterpret_cast<__half2*>(g_Wh);
    for (; i < n2; i += stride) {
        float2 v = w2[i];
        int row = i >> 11;             // (2*i)/4096
        float s = scale[row];
        hi2[i] = __floats2half2_rn(v.x * s, v.y * s);
    }
}

// ---------------------------------------------------------------------------
// Associative memory: logits -> softmax -> weighted value sum
// ---------------------------------------------------------------------------
__global__ void logits_kernel(const float* __restrict__ keys,
                              const float* __restrict__ x) {
    int c = blockIdx.x;
    const float* kr = keys + (size_t)c * K_DIM;
    float s = 0.f;
    for (int i = threadIdx.x; i < K_DIM; i += 128) s += kr[i] * x[i];
    for (int o = 16; o; o >>= 1) s += __shfl_xor_sync(0xffffffffu, s, o);
    __shared__ float red[4];
    if ((threadIdx.x & 31) == 0) red[threadIdx.x >> 5] = s;
    __syncthreads();
    if (threadIdx.x == 0) g_logits[c] = red[0] + red[1] + red[2] + red[3];
}

__global__ void softmax_kernel() {
    int t = threadIdx.x;
    float v = g_logits[t];
    __shared__ float red[32];
    __shared__ float stat;
    float m = v;
    for (int o = 16; o; o >>= 1) m = fmaxf(m, __shfl_xor_sync(0xffffffffu, m, o));
    if ((t & 31) == 0) red[t >> 5] = m;
    __syncthreads();
    if (t < 32) {
        float mm = red[t];
        for (int o = 16; o; o >>= 1) mm = fmaxf(mm, __shfl_xor_sync(0xffffffffu, mm, o));
        if (t == 0) stat = mm;
    }
    __syncthreads();
    float e = __expf(v - stat);
    float s = e;
    for (int o = 16; o; o >>= 1) s += __shfl_xor_sync(0xffffffffu, s, o);
    __syncthreads();
    if ((t & 31) == 0) red[t >> 5] = s;
    __syncthreads();
    if (t < 32) {
        float ss = red[t];
        for (int o = 16; o; o >>= 1) ss += __shfl_xor_sync(0xffffffffu, ss, o);
        if (t == 0) stat = ss;
    }
    __syncthreads();
    g_attn[t] = e / stat;
}

__global__ void memout_kernel(const float* __restrict__ V) {
    __shared__ float sa[CAP_];
    for (int i = threadIdx.x; i < CAP_; i += blockDim.x) sa[i] = g_attn[i];
    __syncthreads();
    int o = blockIdx.x * blockDim.x + threadIdx.x;
    float s = 0.f;
    #pragma unroll 8
    for (int c = 0; c < CAP_; ++c) s += sa[c] * V[(size_t)c * N_DIM + o];
    g_memout[o] = s;
}

// ---------------------------------------------------------------------------
// GEMM: out[m][n] = xh[m]·Wh[n] + 0.01*memout[n]
// fp16 inputs, fp32 accumulate, mma.sync m16n8k16, 2 CTAs/SM
// ---------------------------------------------------------------------------
__device__ __forceinline__ void load_stage(char* smem, int s, int kt,
                                           int tid, int m0, int n0) {
    const int k0 = kt * BK;
    char* st = smem + s * STAGE_BYTES;
    const __half* gA = g_Xh + (size_t)m0 * K_DIM + k0;
    const __half* gB = g_Wh + (size_t)n0 * K_DIM + k0;
    // each tile = 128 rows x 8 chunks(16B) = 1024 chunks
    #pragma unroll
    for (int i = 0; i < 4; ++i) {
        int idx = tid + i * 256;
        int row = idx >> 3, c = idx & 7;
        unsigned off = row * (PAD * 2) + c * 16;
        cp16(smem_u32(st + OFF_A + off), gA + (size_t)row * K_DIM + c * 8);
        cp16(smem_u32(st + OFF_B + off), gB + (size_t)row * K_DIM + c * 8);
    }
}

__global__ __launch_bounds__(256, 2)
void gemm_kernel(float* __restrict__ out) {
    extern __shared__ char smem[];
    const int tid  = threadIdx.x;
    const int lane = tid & 31;
    const int warp = tid >> 5;
    const int wm = warp & 1;          // 2 warps along M (64 rows each)
    const int wn = warp >> 1;         // 4 warps along N (32 cols each)
    const int m0 = blockIdx.y * BM;
    const int n0 = blockIdx.x * BN;

    float acc[4][4][4];
    #pragma unroll
    for (int mi = 0; mi < 4; ++mi)
        #pragma unroll
        for (int ni = 0; ni < 4; ++ni)
            #pragma unroll
            for (int r = 0; r < 4; ++r) acc[mi][ni][r] = 0.f;

    load_stage(smem, 0, 0, tid, m0, n0);
    asm volatile("cp.async.commit_group;");
    load_stage(smem, 1, 1, tid, m0, n0);
    asm volatile("cp.async.commit_group;");

    // per-thread ldmatrix base offsets (element units)
    const int a_row = wm * 64 + (lane & 15);
    const int a_col = (lane >> 4) * 8;
    const int b_row = wn * 32 + (lane & 7);
    const int b_col = ((lane >> 3) & 1) * 8;

    for (int kt = 0; kt < KT; ++kt) {
        asm volatile("cp.async.wait_group %0;" :: "n"(STAGES - 2));
        __syncthreads();
        if (kt + 2 < KT) load_stage(smem, (kt + 2) % STAGES, kt + 2, tid, m0, n0);
        asm volatile("cp.async.commit_group;");

        char* st = smem + (kt % STAGES) * STAGE_BYTES;
        const __half* sA = reinterpret_cast<const __half*>(st + OFF_A);
        const __half* sB = reinterpret_cast<const __half*>(st + OFF_B);

        #pragma unroll
        for (int ks = 0; ks < 4; ++ks) {
            unsigned af[4][4], bf[4][2];
            #pragma unroll
            for (int mi = 0; mi < 4; ++mi) {
                unsigned ad = smem_u32(sA + (a_row + mi * 16) * PAD + ks * 16 + a_col);
                asm volatile("ldmatrix.sync.aligned.m8n8.x4.shared.b16 {%0,%1,%2,%3}, [%4];"
                             : "=r"(af[mi][0]), "=r"(af[mi][1]),
                               "=r"(af[mi][2]), "=r"(af[mi][3]) : "r"(ad));
            }
            #pragma unroll
            for (int ni = 0; ni < 4; ++ni) {
                unsigned bd = smem_u32(sB + (b_row + ni * 8) * PAD + ks * 16 + b_col);
                asm volatile("ldmatrix.sync.aligned.m8n8.x2.shared.b16 {%0,%1}, [%2];"
                             : "=r"(bf[ni][0]), "=r"(bf[ni][1]) : "r"(bd));
            }
            #pragma unroll
            for (int mi = 0; mi < 4; ++mi)
                #pragma unroll
                for (int ni = 0; ni < 4; ++ni)
                    asm volatile(
                        "mma.sync.aligned.m16n8k16.row.col.f32.f16.f16.f32 "
                        "{%0,%1,%2,%3}, {%4,%5,%6,%7}, {%8,%9}, {%0,%1,%2,%3};"
                        : "+f"(acc[mi][ni][0]), "+f"(acc[mi][ni][1]),
                          "+f"(acc[mi][ni][2]), "+f"(acc[mi][ni][3])
                        : "r"(af[mi][0]), "r"(af[mi][1]),
                          "r"(af[mi][2]), "r"(af[mi][3]),
                          "r"(bf[ni][0]), "r"(bf[ni][1]));
        }
    }

    // Epilogue: add 0.01 * memory_out[n]
    const int g = lane >> 2, tg = lane & 3;
    #pragma unroll
    for (int ni = 0; ni < 4; ++ni) {
        int col = n0 + wn * 32 + ni * 8 + tg * 2;
        float b0 = 0.01f * g_memout[col];
        float b1 = 0.01f * g_memout[col + 1];
        #pragma unroll
        for (int mi = 0; mi < 4; ++mi) {
            int row = m0 + wm * 64 + mi * 16 + g;
            float2 v0 = make_float2(acc[mi][ni][0] + b0, acc[mi][ni][1] + b1);
            float2 v1 = make_float2(acc[mi][ni][2] + b0, acc[mi][ni][3] + b1);
            *reinterpret_cast<float2*>(out + (size_t)row * N_DIM + col) = v0;
            *reinterpret_cast<float2*>(out + (size_t)(row + 8) * N_DIM + col) = v1;
        }
    }
}

// ---------------------------------------------------------------------------
extern "C" void kernel_launch(void* const* d_in, const int* in_sizes, int n_in,
                              void* d_out, int out_size) {
    (void)in_sizes; (void)n_in; (void)out_size;
    const float* x  = (const float*)d_in[0];
    const float* w  = (const float*)d_in[1];
    const float* ws = (const float*)d_in[2];
    const float* mk = (const float*)d_in[3];
    const float* mv = (const float*)d_in[4];
    float* out = (float*)d_out;

    split_x_kernel<<<2048, 256>>>(x, (M_DIM * K_DIM) / 2);
    split_w_kernel<<<2048, 256>>>(w, ws, (N_DIM * K_DIM) / 2);

    logits_kernel<<<CAP_, 128>>>(mk, x);
    softmax_kernel<<<1, CAP_>>>();
    memout_kernel<<<N_DIM / 256, 256>>>(mv);

    cudaFuncSetAttribute(gemm_kernel, cudaFuncAttributeMaxDynamicSharedMemorySize,
                         SMEM_TOTAL);
    dim3 grid(N_DIM / BN, M_DIM / BM);   // 32 x 64 = 2048 CTAs
    gemm_kernel<<<grid, 256, SMEM_TOTAL>>>(out);
}

// round 6
// speedup vs baseline: 3.2665x; 1.0115x over previous
#include <cuda_runtime.h>
#include <cuda_fp16.h>
#include <cstdint>

// Problem dims
#define M_DIM 8192
#define N_DIM 4096
#define K_DIM 4096
#define CAP_  1024

// GEMM tiling
#define BM 128
#define BN 128
#define BK 64
#define KT (K_DIM / BK)            // 64
#define STAGES 3
#define PAD 72                     // smem row pitch in elements (144B rows)
#define TILE_BYTES (128 * PAD * 2) // 18432
#define STAGE_BYTES (2 * TILE_BYTES)          // A + B = 36864
#define SMEM_TOTAL (STAGES * STAGE_BYTES)     // 110592 -> 2 CTAs/SM

#define OFF_A 0
#define OFF_B TILE_BYTES

// ---------------------------------------------------------------------------
// Scratch (static device memory)
// ---------------------------------------------------------------------------
__device__ __half g_Xh[(size_t)M_DIM * K_DIM];   // x rounded to fp16
__device__ __half g_Wh[(size_t)N_DIM * K_DIM];   // w*scale rounded to fp16
__device__ float g_logits[CAP_];
__device__ float g_memout[N_DIM];

// ---------------------------------------------------------------------------
__device__ __forceinline__ unsigned smem_u32(const void* p) {
    return (unsigned)__cvta_generic_to_shared(p);
}
__device__ __forceinline__ void cp16(unsigned sa, const void* ga) {
    asm volatile("cp.async.cg.shared.global [%0], [%1], 16;" :: "r"(sa), "l"(ga));
}

// ---------------------------------------------------------------------------
// Prep: x -> fp16; w*scale -> fp16
// ---------------------------------------------------------------------------
__global__ void split_x_kernel(const float* __restrict__ x, int n2) {
    int i = blockIdx.x * blockDim.x + threadIdx.x;
    int stride = gridDim.x * blockDim.x;
    const float2* x2 = reinterpret_cast<const float2*>(x);
    __half2* h2 = reinterpret_cast<__half2*>(g_Xh);
    for (; i < n2; i += stride) {
        float2 v = x2[i];
        h2[i] = __floats2half2_rn(v.x, v.y);
    }
}

__global__ void split_w_kernel(const float* __restrict__ w,
                               const float* __restrict__ scale, int n2) {
    int i = blockIdx.x * blockDim.x + threadIdx.x;
    int stride = gridDim.x * blockDim.x;
    const float2* w2 = reinterpret_cast<const float2*>(w);
    __half2* hi2 = reinterpret_cast<__half2*>(g_Wh);
    for (; i < n2; i += stride) {
        float2 v = w2[i];
        int row = i >> 11;             // (2*i)/4096
        float s = scale[row];
        hi2[i] = __floats2half2_rn(v.x * s, v.y * s);
    }
}

// ---------------------------------------------------------------------------
// Associative memory
// ---------------------------------------------------------------------------
__global__ void logits_kernel(const float* __restrict__ keys,
                              const float* __restrict__ x) {
    int c = blockIdx.x;
    const float* kr = keys + (size_t)c * K_DIM;
    float s = 0.f;
    for (int i = threadIdx.x; i < K_DIM; i += 128) s += kr[i] * x[i];
    for (int o = 16; o; o >>= 1) s += __shfl_xor_sync(0xffffffffu, s, o);
    __shared__ float red[4];
    if ((threadIdx.x & 31) == 0) red[threadIdx.x >> 5] = s;
    __syncthreads();
    if (threadIdx.x == 0) g_logits[c] = red[0] + red[1] + red[2] + red[3];
}

// Fused softmax + attn@V: each block redundantly computes the softmax stats
// (1024 values, trivial) then its 256 output columns.
__global__ void memout_kernel(const float* __restrict__ V) {
    __shared__ float se[CAP_];
    __shared__ float red[32];
    const int t = threadIdx.x;       // 256 threads
    // local logits -> exp
    float lmax = -1e30f;
    float lv[4];
    #pragma unroll
    for (int j = 0; j < 4; ++j) {
        lv[j] = g_logits[t + j * 256];
        lmax = fmaxf(lmax, lv[j]);
    }
    for (int o = 16; o; o >>= 1) lmax = fmaxf(lmax, __shfl_xor_sync(0xffffffffu, lmax, o));
    if ((t & 31) == 0) red[t >> 5] = lmax;
    __syncthreads();
    float m = fmaxf(fmaxf(red[0], red[1]), fmaxf(red[2], red[3]));
    m = fmaxf(m, fmaxf(fmaxf(red[4], red[5]), fmaxf(red[6], red[7])));
    float psum = 0.f;
    #pragma unroll
    for (int j = 0; j < 4; ++j) {
        float e = __expf(lv[j] - m);
        se[t + j * 256] = e;
        psum += e;
    }
    for (int o = 16; o; o >>= 1) psum += __shfl_xor_sync(0xffffffffu, psum, o);
    __syncthreads();
    if ((t & 31) == 0) red[t >> 5] = psum;
    __syncthreads();
    float sum = (red[0] + red[1]) + (red[2] + red[3])
              + (red[4] + red[5]) + (red[6] + red[7]);
    float inv = 1.f / sum;
    int o = blockIdx.x * 256 + t;
    float s = 0.f;
    #pragma unroll 8
    for (int c = 0; c < CAP_; ++c) s += se[c] * V[(size_t)c * N_DIM + o];
    g_memout[o] = s * inv;
}

// ---------------------------------------------------------------------------
// GEMM: out[m][n] = xh[m]·Wh[n] + 0.01*memout[n]
// fp16 inputs, fp32 accumulate, mma.sync m16n8k16, 2 CTAs/SM
// ---------------------------------------------------------------------------
__device__ __forceinline__ void load_stage(char* smem, int s, int kt,
                                           int tid, int m0, int n0) {
    const int k0 = kt * BK;
    char* st = smem + s * STAGE_BYTES;
    const __half* gA = g_Xh + (size_t)m0 * K_DIM + k0;
    const __half* gB = g_Wh + (size_t)n0 * K_DIM + k0;
    #pragma unroll
    for (int i = 0; i < 4; ++i) {
        int idx = tid + i * 256;
        int row = idx >> 3, c = idx & 7;
        unsigned off = row * (PAD * 2) + c * 16;
        cp16(smem_u32(st + OFF_A + off), gA + (size_t)row * K_DIM + c * 8);
        cp16(smem_u32(st + OFF_B + off), gB + (size_t)row * K_DIM + c * 8);
    }
}

__global__ __launch_bounds__(256, 2)
void gemm_kernel(float* __restrict__ out) {
    extern __shared__ char smem[];
    const int tid  = threadIdx.x;
    const int lane = tid & 31;
    const int warp = tid >> 5;
    const int wm = warp & 1;          // 2 warps along M (64 rows each)
    const int wn = warp >> 1;         // 4 warps along N (32 cols each)
    const int m0 = blockIdx.y * BM;
    const int n0 = blockIdx.x * BN;

    float acc[4][4][4];
    #pragma unroll
    for (int mi = 0; mi < 4; ++mi)
        #pragma unroll
        for (int ni = 0; ni < 4; ++ni)
            #pragma unroll
            for (int r = 0; r < 4; ++r) acc[mi][ni][r] = 0.f;

    load_stage(smem, 0, 0, tid, m0, n0);
    asm volatile("cp.async.commit_group;");
    load_stage(smem, 1, 1, tid, m0, n0);
    asm volatile("cp.async.commit_group;");

    // A ldmatrix.x4 addressing: lanes 0-15 rows, 16-31 rows at col+8
    const int a_row = wm * 64 + (lane & 15);
    const int a_col = (lane >> 4) * 8;
    // B ldmatrix.x4 addressing: lane group g=lane>>3 selects matrix:
    //   g0: rows n..n+7 col+0 ; g1: same rows col+8 ; g2: rows+8 col+0 ; g3: rows+8 col+8
    const int bg  = lane >> 3;
    const int b4_row = wn * 32 + ((bg >> 1) << 3) + (lane & 7);
    const int b4_col = (bg & 1) << 3;

    for (int kt = 0; kt < KT; ++kt) {
        asm volatile("cp.async.wait_group %0;" :: "n"(STAGES - 2));
        __syncthreads();
        if (kt + 2 < KT) load_stage(smem, (kt + 2) % STAGES, kt + 2, tid, m0, n0);
        asm volatile("cp.async.commit_group;");

        char* st = smem + (kt % STAGES) * STAGE_BYTES;
        const __half* sA = reinterpret_cast<const __half*>(st + OFF_A);
        const __half* sB = reinterpret_cast<const __half*>(st + OFF_B);

        unsigned bq[2][4][2];   // double-buffered B fragments

        auto load_B = [&](int ks, int buf) {
            #pragma unroll
            for (int p = 0; p < 2; ++p) {
                unsigned bd = smem_u32(sB + (b4_row + p * 16) * PAD + ks * 16 + b4_col);
                asm volatile("ldmatrix.sync.aligned.m8n8.x4.shared.b16 {%0,%1,%2,%3}, [%4];"
                             : "=r"(bq[buf][2*p][0]),   "=r"(bq[buf][2*p][1]),
                               "=r"(bq[buf][2*p+1][0]), "=r"(bq[buf][2*p+1][1])
                             : "r"(bd));
            }
        };

        load_B(0, 0);
        #pragma unroll
        for (int ks = 0; ks < 4; ++ks) {
            const int cur = ks & 1;
            unsigned af[4][4];
            #pragma unroll
            for (int mi = 0; mi < 4; ++mi) {
                unsigned ad = smem_u32(sA + (a_row + mi * 16) * PAD + ks * 16 + a_col);
                asm volatile("ldmatrix.sync.aligned.m8n8.x4.shared.b16 {%0,%1,%2,%3}, [%4];"
                             : "=r"(af[mi][0]), "=r"(af[mi][1]),
                               "=r"(af[mi][2]), "=r"(af[mi][3]) : "r"(ad));
            }
            if (ks < 3) load_B(ks + 1, cur ^ 1);
            #pragma unroll
            for (int mi = 0; mi < 4; ++mi)
                #pragma unroll
                for (int ni = 0; ni < 4; ++ni)
                    asm volatile(
                        "mma.sync.aligned.m16n8k16.row.col.f32.f16.f16.f32 "
                        "{%0,%1,%2,%3}, {%4,%5,%6,%7}, {%8,%9}, {%0,%1,%2,%3};"
                        : "+f"(acc[mi][ni][0]), "+f"(acc[mi][ni][1]),
                          "+f"(acc[mi][ni][2]), "+f"(acc[mi][ni][3])
                        : "r"(af[mi][0]), "r"(af[mi][1]),
                          "r"(af[mi][2]), "r"(af[mi][3]),
                          "r"(bq[cur][ni][0]), "r"(bq[cur][ni][1]));
        }
    }

    // Epilogue: add 0.01 * memory_out[n]
    const int g = lane >> 2, tg = lane & 3;
    #pragma unroll
    for (int ni = 0; ni < 4; ++ni) {
        int col = n0 + wn * 32 + ni * 8 + tg * 2;
        float b0 = 0.01f * g_memout[col];
        float b1 = 0.01f * g_memout[col + 1];
        #pragma unroll
        for (int mi = 0; mi < 4; ++mi) {
            int row = m0 + wm * 64 + mi * 16 + g;
            float2 v0 = make_float2(acc[mi][ni][0] + b0, acc[mi][ni][1] + b1);
            float2 v1 = make_float2(acc[mi][ni][2] + b0, acc[mi][ni][3] + b1);
            *reinterpret_cast<float2*>(out + (size_t)row * N_DIM + col) = v0;
            *reinterpret_cast<float2*>(out + (size_t)(row + 8) * N_DIM + col) = v1;
        }
    }
}

// ---------------------------------------------------------------------------
extern "C" void kernel_launch(void* const* d_in, const int* in_sizes, int n_in,
                              void* d_out, int out_size) {
    (void)in_sizes; (void)n_in; (void)out_size;
    const float* x  = (const float*)d_in[0];
    const float* w  = (const float*)d_in[1];
    const float* ws = (const float*)d_in[2];
    const float* mk = (const float*)d_in[3];
    const float* mv = (const float*)d_in[4];
    float* out = (float*)d_out;

    split_x_kernel<<<2048, 256>>>(x, (M_DIM * K_DIM) / 2);
    split_w_kernel<<<2048, 256>>>(w, ws, (N_DIM * K_DIM) / 2);

    logits_kernel<<<CAP_, 128>>>(mk, x);
    memout_kernel<<<N_DIM / 256, 256>>>(mv);

    cudaFuncSetAttribute(gemm_kernel, cudaFuncAttributeMaxDynamicSharedMemorySize,
                         SMEM_TOTAL);
    dim3 grid(N_DIM / BN, M_DIM / BM);   // 32 x 64 = 2048 CTAs
    gemm_kernel<<<grid, 256, SMEM_TOTAL>>>(out);
}

// round 7
// speedup vs baseline: 3.5374x; 1.0829x over previous
#include <cuda_runtime.h>
#include <cuda_fp16.h>
#include <cstdint>

// Problem dims
#define M_DIM 8192
#define N_DIM 4096
#define K_DIM 4096
#define CAP_  1024

// GEMM tiling
#define BM 128
#define BN 128
#define BK 64
#define KT (K_DIM / BK)            // 64
#define STAGES 3
#define PAD 72                     // smem row pitch in elements (144B rows)
#define TILE_BYTES (128 * PAD * 2) // 18432
#define STAGE_BYTES (2 * TILE_BYTES)          // A + B = 36864
#define SMEM_TOTAL (STAGES * STAGE_BYTES)     // 110592 -> 2 CTAs/SM

#define OFF_A 0
#define OFF_B TILE_BYTES

// ---------------------------------------------------------------------------
// Scratch (static device memory)
// ---------------------------------------------------------------------------
__device__ __half g_Xh[(size_t)M_DIM * K_DIM];   // x rounded to fp16
__device__ __half g_Wh[(size_t)N_DIM * K_DIM];   // w*scale rounded to fp16
__device__ float g_logits[CAP_];
__device__ float g_memout[N_DIM];

// ---------------------------------------------------------------------------
__device__ __forceinline__ unsigned smem_u32(const void* p) {
    return (unsigned)__cvta_generic_to_shared(p);
}
__device__ __forceinline__ void cp16(unsigned sa, const void* ga) {
    asm volatile("cp.async.cg.shared.global [%0], [%1], 16;" :: "r"(sa), "l"(ga));
}

// ---------------------------------------------------------------------------
// Prep: x -> fp16; w*scale -> fp16
// ---------------------------------------------------------------------------
__global__ void split_x_kernel(const float* __restrict__ x, int n2) {
    int i = blockIdx.x * blockDim.x + threadIdx.x;
    int stride = gridDim.x * blockDim.x;
    const float2* x2 = reinterpret_cast<const float2*>(x);
    __half2* h2 = reinterpret_cast<__half2*>(g_Xh);
    for (; i < n2; i += stride) {
        float2 v = x2[i];
        h2[i] = __floats2half2_rn(v.x, v.y);
    }
}

__global__ void split_w_kernel(const float* __restrict__ w,
                               const float* __restrict__ scale, int n2) {
    int i = blockIdx.x * blockDim.x + threadIdx.x;
    int stride = gridDim.x * blockDim.x;
    const float2* w2 = reinterpret_cast<const float2*>(w);
    __half2* hi2 = reinterpret_cast<__half2*>(g_Wh);
    for (; i < n2; i += stride) {
        float2 v = w2[i];
        int row = i >> 11;             // (2*i)/4096
        float s = scale[row];
        hi2[i] = __floats2half2_rn(v.x * s, v.y * s);
    }
}

// ---------------------------------------------------------------------------
// Associative memory
// ---------------------------------------------------------------------------
__global__ void logits_kernel(const float* __restrict__ keys,
                              const float* __restrict__ x) {
    int c = blockIdx.x;
    const float* kr = keys + (size_t)c * K_DIM;
    float s = 0.f;
    for (int i = threadIdx.x; i < K_DIM; i += 128) s += kr[i] * x[i];
    for (int o = 16; o; o >>= 1) s += __shfl_xor_sync(0xffffffffu, s, o);
    __shared__ float red[4];
    if ((threadIdx.x & 31) == 0) red[threadIdx.x >> 5] = s;
    __syncthreads();
    if (threadIdx.x == 0) g_logits[c] = red[0] + red[1] + red[2] + red[3];
}

// Fused softmax + attn@V, re-gridded for full-chip parallelism:
// 128 CTAs x 256 threads; CTA owns 32 output cols; threads split CAP into
// 8 chunks of 128 (t&31 = col lane, t>>5 = chunk); deterministic smem reduce.
__global__ void memout_kernel(const float* __restrict__ V) {
    __shared__ float se[CAP_];
    __shared__ float red[8];
    __shared__ float part[8][33];
    const int t = threadIdx.x;       // 256 threads

    // redundant per-CTA softmax over the 1024 logits (cheap)
    float lmax = -1e30f;
    float lv[4];
    #pragma unroll
    for (int j = 0; j < 4; ++j) {
        lv[j] = g_logits[t + j * 256];
        lmax = fmaxf(lmax, lv[j]);
    }
    for (int o = 16; o; o >>= 1) lmax = fmaxf(lmax, __shfl_xor_sync(0xffffffffu, lmax, o));
    if ((t & 31) == 0) red[t >> 5] = lmax;
    __syncthreads();
    float m = fmaxf(fmaxf(red[0], red[1]), fmaxf(red[2], red[3]));
    m = fmaxf(m, fmaxf(fmaxf(red[4], red[5]), fmaxf(red[6], red[7])));
    float psum = 0.f;
    #pragma unroll
    for (int j = 0; j < 4; ++j) {
        float e = __expf(lv[j] - m);
        se[t + j * 256] = e;
        psum += e;
    }
    for (int o = 16; o; o >>= 1) psum += __shfl_xor_sync(0xffffffffu, psum, o);
    __syncthreads();
    if ((t & 31) == 0) red[t >> 5] = psum;
    __syncthreads();
    float inv = 1.f / ((red[0] + red[1]) + (red[2] + red[3])
                     + (red[4] + red[5]) + (red[6] + red[7]));

    // attn @ V on 32 columns, 8-way cap split
    const int colLane = t & 31;
    const int chunk = t >> 5;        // 0..7
    const int col = blockIdx.x * 32 + colLane;
    const float* Vc = V + (size_t)(chunk * 128) * N_DIM + col;
    float s = 0.f;
    #pragma unroll 8
    for (int c = 0; c < 128; ++c)
        s += se[chunk * 128 + c] * Vc[(size_t)c * N_DIM];
    part[chunk][colLane] = s;
    __syncthreads();
    if (chunk == 0) {
        float tot = 0.f;
        #pragma unroll
        for (int j = 0; j < 8; ++j) tot += part[j][colLane];
        g_memout[col] = tot * inv;
    }
}

// ---------------------------------------------------------------------------
// GEMM: out[m][n] = xh[m]·Wh[n] + 0.01*memout[n]
// fp16 inputs, fp32 accumulate, mma.sync m16n8k16, 2 CTAs/SM
// ---------------------------------------------------------------------------
__device__ __forceinline__ void load_stage(char* smem, int s, int kt,
                                           int tid, int m0, int n0) {
    const int k0 = kt * BK;
    char* st = smem + s * STAGE_BYTES;
    const __half* gA = g_Xh + (size_t)m0 * K_DIM + k0;
    const __half* gB = g_Wh + (size_t)n0 * K_DIM + k0;
    #pragma unroll
    for (int i = 0; i < 4; ++i) {
        int idx = tid + i * 256;
        int row = idx >> 3, c = idx & 7;
        unsigned off = row * (PAD * 2) + c * 16;
        cp16(smem_u32(st + OFF_A + off), gA + (size_t)row * K_DIM + c * 8);
        cp16(smem_u32(st + OFF_B + off), gB + (size_t)row * K_DIM + c * 8);
    }
}

__global__ __launch_bounds__(256, 2)
void gemm_kernel(float* __restrict__ out) {
    extern __shared__ char smem[];
    const int tid  = threadIdx.x;
    const int lane = tid & 31;
    const int warp = tid >> 5;
    const int wm = warp & 1;          // 2 warps along M (64 rows each)
    const int wn = warp >> 1;         // 4 warps along N (32 cols each)
    const int m0 = blockIdx.y * BM;
    const int n0 = blockIdx.x * BN;

    float acc[4][4][4];
    #pragma unroll
    for (int mi = 0; mi < 4; ++mi)
        #pragma unroll
        for (int ni = 0; ni < 4; ++ni)
            #pragma unroll
            for (int r = 0; r < 4; ++r) acc[mi][ni][r] = 0.f;

    load_stage(smem, 0, 0, tid, m0, n0);
    asm volatile("cp.async.commit_group;");
    load_stage(smem, 1, 1, tid, m0, n0);
    asm volatile("cp.async.commit_group;");

    const int a_row = wm * 64 + (lane & 15);
    const int a_col = (lane >> 4) * 8;
    const int bg  = lane >> 3;
    const int b4_row = wn * 32 + ((bg >> 1) << 3) + (lane & 7);
    const int b4_col = (bg & 1) << 3;

    for (int kt = 0; kt < KT; ++kt) {
        asm volatile("cp.async.wait_group %0;" :: "n"(STAGES - 2));
        __syncthreads();
        if (kt + 2 < KT) load_stage(smem, (kt + 2) % STAGES, kt + 2, tid, m0, n0);
        asm volatile("cp.async.commit_group;");

        char* st = smem + (kt % STAGES) * STAGE_BYTES;
        const __half* sA = reinterpret_cast<const __half*>(st + OFF_A);
        const __half* sB = reinterpret_cast<const __half*>(st + OFF_B);

        unsigned bq[2][4][2];   // double-buffered B fragments

        auto load_B = [&](int ks, int buf) {
            #pragma unroll
            for (int p = 0; p < 2; ++p) {
                unsigned bd = smem_u32(sB + (b4_row + p * 16) * PAD + ks * 16 + b4_col);
                asm volatile("ldmatrix.sync.aligned.m8n8.x4.shared.b16 {%0,%1,%2,%3}, [%4];"
                             : "=r"(bq[buf][2*p][0]),   "=r"(bq[buf][2*p][1]),
                               "=r"(bq[buf][2*p+1][0]), "=r"(bq[buf][2*p+1][1])
                             : "r"(bd));
            }
        };

        load_B(0, 0);
        #pragma unroll
        for (int ks = 0; ks < 4; ++ks) {
            const int cur = ks & 1;
            unsigned af[4][4];
            #pragma unroll
            for (int mi = 0; mi < 4; ++mi) {
                unsigned ad = smem_u32(sA + (a_row + mi * 16) * PAD + ks * 16 + a_col);
                asm volatile("ldmatrix.sync.aligned.m8n8.x4.shared.b16 {%0,%1,%2,%3}, [%4];"
                             : "=r"(af[mi][0]), "=r"(af[mi][1]),
                               "=r"(af[mi][2]), "=r"(af[mi][3]) : "r"(ad));
            }
            if (ks < 3) load_B(ks + 1, cur ^ 1);
            #pragma unroll
            for (int mi = 0; mi < 4; ++mi)
                #pragma unroll
                for (int ni = 0; ni < 4; ++ni)
                    asm volatile(
                        "mma.sync.aligned.m16n8k16.row.col.f32.f16.f16.f32 "
                        "{%0,%1,%2,%3}, {%4,%5,%6,%7}, {%8,%9}, {%0,%1,%2,%3};"
                        : "+f"(acc[mi][ni][0]), "+f"(acc[mi][ni][1]),
                          "+f"(acc[mi][ni][2]), "+f"(acc[mi][ni][3])
                        : "r"(af[mi][0]), "r"(af[mi][1]),
                          "r"(af[mi][2]), "r"(af[mi][3]),
                          "r"(bq[cur][ni][0]), "r"(bq[cur][ni][1]));
        }
    }

    // Epilogue: add 0.01 * memory_out[n]
    const int g = lane >> 2, tg = lane & 3;
    #pragma unroll
    for (int ni = 0; ni < 4; ++ni) {
        int col = n0 + wn * 32 + ni * 8 + tg * 2;
        float b0 = 0.01f * g_memout[col];
        float b1 = 0.01f * g_memout[col + 1];
        #pragma unroll
        for (int mi = 0; mi < 4; ++mi) {
            int row = m0 + wm * 64 + mi * 16 + g;
            float2 v0 = make_float2(acc[mi][ni][0] + b0, acc[mi][ni][1] + b1);
            float2 v1 = make_float2(acc[mi][ni][2] + b0, acc[mi][ni][3] + b1);
            *reinterpret_cast<float2*>(out + (size_t)row * N_DIM + col) = v0;
            *reinterpret_cast<float2*>(out + (size_t)(row + 8) * N_DIM + col) = v1;
        }
    }
}

// ---------------------------------------------------------------------------
extern "C" void kernel_launch(void* const* d_in, const int* in_sizes, int n_in,
                              void* d_out, int out_size) {
    (void)in_sizes; (void)n_in; (void)out_size;
    const float* x  = (const float*)d_in[0];
    const float* w  = (const float*)d_in[1];
    const float* ws = (const float*)d_in[2];
    const float* mk = (const float*)d_in[3];
    const float* mv = (const float*)d_in[4];
    float* out = (float*)d_out;

    split_x_kernel<<<2048, 256>>>(x, (M_DIM * K_DIM) / 2);
    split_w_kernel<<<2048, 256>>>(w, ws, (N_DIM * K_DIM) / 2);

    logits_kernel<<<CAP_, 128>>>(mk, x);
    memout_kernel<<<N_DIM / 32, 256>>>(mv);

    cudaFuncSetAttribute(gemm_kernel, cudaFuncAttributeMaxDynamicSharedMemorySize,
                         SMEM_TOTAL);
    dim3 grid(N_DIM / BN, M_DIM / BM);   // 32 x 64 = 2048 CTAs
    gemm_kernel<<<grid, 256, SMEM_TOTAL>>>(out);
}